// round 2
// baseline (speedup 1.0000x reference)
#include <cuda_runtime.h>

#define N 4096
#define K 512
#define KSEL 31   // n_nbg + 1

// ---- scratch (no allocations allowed) ----
__device__ float g_d2[(size_t)N * N];   // 64 MB pairwise squared distances
__device__ float g_sq[N];               // row norms
__device__ float g_t[N];                // 31st-smallest d2 per row (mask threshold)
__device__ float g_inv[N];              // 1 / denom (gaussian inverse scale)

// ============================================================
// Kernel 1: row squared norms. One block (128 threads) per row.
// ============================================================
__global__ void norms_kernel(const float* __restrict__ X) {
    int row = blockIdx.x;
    int t = threadIdx.x;                       // 0..127, K/4 = 128 float4
    const float4* x4 = reinterpret_cast<const float4*>(X + (size_t)row * K);
    float4 v = x4[t];
    float s = v.x * v.x + v.y * v.y + v.z * v.z + v.w * v.w;
    #pragma unroll
    for (int o = 16; o; o >>= 1) s += __shfl_xor_sync(0xffffffffu, s, o);
    __shared__ float ws[4];
    if ((t & 31) == 0) ws[t >> 5] = s;
    __syncthreads();
    if (t == 0) g_sq[row] = ws[0] + ws[1] + ws[2] + ws[3];
}

// ============================================================
// Kernel 2: d2 = max(sq_i + sq_j - 2*X·X^T, 0), symmetric.
// 128x128 output tile, BK=16, 256 threads, 8x8 microtile.
// Only upper-triangular block tiles computed; each writes its
// tile and the transposed tile.
// ============================================================
#define BM 128
#define BK 16
#define LDA (BM + 4)

__global__ void __launch_bounds__(256, 2) d2_kernel(const float* __restrict__ X) {
    const int by = blockIdx.y, bx = blockIdx.x;
    if (bx < by) return;                 // triangular: bx >= by

    __shared__ float As[BK][LDA];
    __shared__ float Bs[BK][LDA];

    const int t  = threadIdx.x;
    const int tx = t & 15;               // 0..15 -> 8 cols each
    const int ty = t >> 4;               // 0..15 -> 8 rows each
    const int i0 = by * BM;
    const int j0 = bx * BM;

    float acc[8][8];
    #pragma unroll
    for (int i = 0; i < 8; i++)
        #pragma unroll
        for (int j = 0; j < 8; j++) acc[i][j] = 0.f;

    for (int kk = 0; kk < K; kk += BK) {
        // load 128 rows x 16 k for A and B operands (512 float4 each)
        #pragma unroll
        for (int l = 0; l < 2; l++) {
            int v  = t + l * 256;        // 0..511
            int r  = v >> 2;
            int c4 = (v & 3) * 4;
            float4 a = *reinterpret_cast<const float4*>(X + (size_t)(i0 + r) * K + kk + c4);
            As[c4 + 0][r] = a.x; As[c4 + 1][r] = a.y;
            As[c4 + 2][r] = a.z; As[c4 + 3][r] = a.w;
            float4 b = *reinterpret_cast<const float4*>(X + (size_t)(j0 + r) * K + kk + c4);
            Bs[c4 + 0][r] = b.x; Bs[c4 + 1][r] = b.y;
            Bs[c4 + 2][r] = b.z; Bs[c4 + 3][r] = b.w;
        }
        __syncthreads();

        #pragma unroll
        for (int k = 0; k < BK; k++) {
            float a[8], b[8];
            #pragma unroll
            for (int i = 0; i < 8; i++) a[i] = As[k][ty * 8 + i];
            #pragma unroll
            for (int j = 0; j < 8; j++) b[j] = Bs[k][tx * 8 + j];
            #pragma unroll
            for (int i = 0; i < 8; i++)
                #pragma unroll
                for (int j = 0; j < 8; j++) acc[i][j] = fmaf(a[i], b[j], acc[i][j]);
        }
        __syncthreads();
    }

    // epilogue: d2 = max(sq_i + sq_j - 2*dot, 0); write tile + transpose
    float sqi[8], sqj[8];
    #pragma unroll
    for (int i = 0; i < 8; i++) sqi[i] = g_sq[i0 + ty * 8 + i];
    #pragma unroll
    for (int j = 0; j < 8; j++) sqj[j] = g_sq[j0 + tx * 8 + j];

    float d[8][8];
    #pragma unroll
    for (int i = 0; i < 8; i++)
        #pragma unroll
        for (int j = 0; j < 8; j++)
            d[i][j] = fmaxf(fmaf(-2.0f, acc[i][j], sqi[i] + sqj[j]), 0.0f);

    // normal tile: rows i0+ty*8+i, cols j0+tx*8 .. +7 (two float4 per row)
    #pragma unroll
    for (int i = 0; i < 8; i++) {
        float* p = g_d2 + (size_t)(i0 + ty * 8 + i) * N + j0 + tx * 8;
        *reinterpret_cast<float4*>(p)     = make_float4(d[i][0], d[i][1], d[i][2], d[i][3]);
        *reinterpret_cast<float4*>(p + 4) = make_float4(d[i][4], d[i][5], d[i][6], d[i][7]);
    }
    // transposed tile: rows j0+tx*8+j, cols i0+ty*8 .. +7
    #pragma unroll
    for (int j = 0; j < 8; j++) {
        float* p = g_d2 + (size_t)(j0 + tx * 8 + j) * N + i0 + ty * 8;
        *reinterpret_cast<float4*>(p)     = make_float4(d[0][j], d[1][j], d[2][j], d[3][j]);
        *reinterpret_cast<float4*>(p + 4) = make_float4(d[4][j], d[5][j], d[6][j], d[7][j]);
    }
}

// ============================================================
// Kernel 3: per-row exact 31st-smallest d2 via bitwise binary
// search on float bit patterns (all values >= 0 so uint order
// == float order). One block (256 threads) per row.
// Each bit-iteration gets its own shared counter slot -> no
// reset race between iterations (the Round-1 bug).
// ============================================================
__global__ void __launch_bounds__(256) select_kernel() {
    const int row = blockIdx.x;
    const int t = threadIdx.x;
    __shared__ unsigned su[N];           // 16 KB
    __shared__ int cnts[31];

    const float* drow = g_d2 + (size_t)row * N;
    for (int i = t; i < N; i += 256) su[i] = __float_as_uint(drow[i]);
    if (t < 31) cnts[t] = 0;
    __syncthreads();

    unsigned T = 0;
    for (int b = 30; b >= 0; b--) {
        const unsigned cand = T | (1u << b);
        const int slot = 30 - b;
        int c = 0;
        #pragma unroll 4
        for (int i = t; i < N; i += 256) c += (su[i] < cand);
        #pragma unroll
        for (int o = 16; o; o >>= 1) c += __shfl_xor_sync(0xffffffffu, c, o);
        if ((t & 31) == 0) atomicAdd(&cnts[slot], c);
        __syncthreads();                 // all atomics to cnts[slot] done
        if (cnts[slot] < KSEL) T = cand; // every thread reads same settled value;
                                         // next iteration uses a different slot
    }

    if (t == 0) {
        float tv = __uint_as_float(T);   // 31st smallest d2 (== scale^2 pre-clamp)
        g_t[row] = tv;
        float scale = sqrtf(fmaxf(tv, 1e-12f));
        float denom = fmaxf(scale, 1e-8f);
        denom *= denom;
        g_inv[row] = 1.0f / denom;
    }
}

// ============================================================
// Kernel 4: out[i][j] = 0.5*( [d<=t_i]*exp(-d*inv_i)
//                           + [d<=t_j]*exp(-d*inv_j) )
// One float4 per thread.
// ============================================================
__global__ void __launch_bounds__(256) out_kernel(float* __restrict__ outp) {
    size_t gid = (size_t)blockIdx.x * 256 + threadIdx.x;  // float4 index
    int row = (int)(gid >> 10);                           // N/4 = 1024 f4/row
    int c0  = (int)(gid & 1023) << 2;

    float ti   = g_t[row];
    float invi = g_inv[row];
    float4 d  = *reinterpret_cast<const float4*>(g_d2 + (size_t)row * N + c0);
    float4 tj = *reinterpret_cast<const float4*>(g_t + c0);
    float4 ij = *reinterpret_cast<const float4*>(g_inv + c0);

    float4 o;
    o.x = 0.5f * ((d.x <= ti ? __expf(-d.x * invi) : 0.f) + (d.x <= tj.x ? __expf(-d.x * ij.x) : 0.f));
    o.y = 0.5f * ((d.y <= ti ? __expf(-d.y * invi) : 0.f) + (d.y <= tj.y ? __expf(-d.y * ij.y) : 0.f));
    o.z = 0.5f * ((d.z <= ti ? __expf(-d.z * invi) : 0.f) + (d.z <= tj.z ? __expf(-d.z * ij.z) : 0.f));
    o.w = 0.5f * ((d.w <= ti ? __expf(-d.w * invi) : 0.f) + (d.w <= tj.w ? __expf(-d.w * ij.w) : 0.f));
    *reinterpret_cast<float4*>(outp + (size_t)row * N + c0) = o;
}

// ============================================================
extern "C" void kernel_launch(void* const* d_in, const int* in_sizes, int n_in,
                              void* d_out, int out_size) {
    const float* X = (const float*)d_in[0];
    float* outp = (float*)d_out;

    norms_kernel<<<N, 128>>>(X);

    dim3 grid2(N / BM, N / BM);          // triangular early-exit inside
    d2_kernel<<<grid2, 256>>>(X);

    select_kernel<<<N, 256>>>();

    out_kernel<<<(size_t)N * N / 4 / 256, 256>>>(outp);
}